// round 15
// baseline (speedup 1.0000x reference)
#include <cuda_runtime.h>
#include <math.h>
#include <stdint.h>

#define SEQ   256
#define NB    32
#define REC   16
#define EMB   32
#define VOCAB 32000
#define ROWS  (SEQ*NB)        /* 8192 */

#define BLK_M   64
#define BLK_N   512
#define NBLK_N  63                 /* ceil(32000/512) */
#define MT_PER_BLK 4
#define NBLK_M  (ROWS/(BLK_M*MT_PER_BLK))   /* 32 */
#define NPART   (NBLK_N*4)
#define VTHREADS 512
#define VS_STRIDE 520              /* pass A/B V^T stride (words) */
#define SB_STRIDE 264              /* pass B staging stride (words) */

#define DYN_SMEM_B ((REC*VS_STRIDE + BLK_M*SB_STRIDE)*4)   /* 100864 B */

#define LOG2E 1.4426950408889634f

__device__ float g_ih[ROWS*REC];
__device__ float g_hidden[ROWS*REC];
__device__ float g_part[ROWS*NPART];
__device__ float g_lse[ROWS];

/* ---- helpers ---- */
__device__ __forceinline__ uint32_t f2tf32(float x) {
    uint32_t r; asm("cvt.rna.tf32.f32 %0, %1;" : "=r"(r) : "f"(x)); return r;
}
__device__ __forceinline__ float ex2(float x) {
    float r; asm("ex2.approx.f32 %0, %1;" : "=f"(r) : "f"(x)); return r;
}
__device__ __forceinline__ void mma_tf32(float* d, const uint32_t* a,
                                         uint32_t b0, uint32_t b1) {
    asm volatile(
        "mma.sync.aligned.m16n8k8.row.col.f32.tf32.tf32.f32 "
        "{%0,%1,%2,%3}, {%4,%5,%6,%7}, {%8,%9}, {%0,%1,%2,%3};\n"
        : "+f"(d[0]), "+f"(d[1]), "+f"(d[2]), "+f"(d[3])
        : "r"(a[0]), "r"(a[1]), "r"(a[2]), "r"(a[3]), "r"(b0), "r"(b1));
}

/* ---------------- kernel 0: no-op (keeps ncu slot on k_vocab0) ------- */
__global__ void k_dummy() {}

/* ---------------- kernel 1: i_h = emb[idx] @ U^T + b1 ---------------- */
__global__ void k_ih(const int* __restrict__ inp, const float* __restrict__ emb,
                     const float* __restrict__ U, const float* __restrict__ b1)
{
    int gid = blockIdx.x*blockDim.x + threadIdx.x;
    if (gid >= ROWS*REC) return;
    int row = gid >> 4;
    int r   = gid & 15;
    int idx = inp[row];
    const float4* e4 = (const float4*)(emb + (size_t)idx*EMB);
    const float4* u4 = (const float4*)(U + r*EMB);
    float acc = b1[r];
    #pragma unroll
    for (int q = 0; q < 8; q++) {
        float4 e = e4[q], u = u4[q];
        acc += e.x*u.x + e.y*u.y + e.z*u.z + e.w*u.w;
    }
    g_ih[gid] = acc;
}

/* ---------------- kernel 2: sequential recurrence (1 warp / batch) ---- */
__global__ void k_rnn(const float* __restrict__ W, const float* __restrict__ b2,
                      const float* __restrict__ h0)
{
    int b = blockIdx.x;
    int r = threadIdx.x;
    __shared__ __align__(16) float ihs[SEQ*REC];
    __shared__ float hs[REC];
    for (int s = r; s < SEQ; s += 32) {
        const float4* src = (const float4*)(g_ih + (size_t)(s*NB + b)*REC);
        float4* dst = (float4*)(ihs + s*REC);
        dst[0]=src[0]; dst[1]=src[1]; dst[2]=src[2]; dst[3]=src[3];
    }
    float wrow[REC]; float bias = 0.f;
    if (r < REC) {
        hs[r] = h0[r];
        #pragma unroll
        for (int k = 0; k < REC; k++) wrow[k] = W[r*REC + k];
        bias = b2[r];
    }
    __syncwarp();
    for (int s = 0; s < SEQ; s++) {
        float hn = 0.f;
        if (r < REC) {
            int row = s*NB + b;
            g_hidden[row*REC + r] = hs[r];
            float acc = ihs[s*REC + r] + bias;
            #pragma unroll
            for (int k = 0; k < REC; k++) acc += wrow[k]*hs[k];
            hn = tanhf(acc);
        }
        __syncwarp();
        if (r < REC) hs[r] = hn;
        __syncwarp();
    }
}

/* ---- shared staging of V^T (tf32) ---- */
__device__ __forceinline__ void stage_V(uint32_t* Vs, const float* __restrict__ V,
                                        int nBase, int tid)
{
    int gn = nBase + tid;
    float4 q0, q1, q2, q3;
    if (gn < VOCAB) {
        const float4* p = (const float4*)(V + (size_t)gn*REC);
        q0 = p[0]; q1 = p[1]; q2 = p[2]; q3 = p[3];
    } else {
        q0 = q1 = q2 = q3 = make_float4(0.f,0.f,0.f,0.f);
    }
    float vv[REC] = {q0.x,q0.y,q0.z,q0.w, q1.x,q1.y,q1.z,q1.w,
                     q2.x,q2.y,q2.z,q2.w, q3.x,q3.y,q3.z,q3.w};
    #pragma unroll
    for (int k = 0; k < REC; k++)
        Vs[k*VS_STRIDE + tid] = f2tf32(vv[k]);
}

/* ---------------- pass A: sum-of-exp partials via tf32 mma ------------ */
__global__ void __launch_bounds__(VTHREADS, 2)
k_vocab0(const float* __restrict__ V)
{
    __shared__ __align__(16) uint32_t Vs[REC*VS_STRIDE];   /* 33.3 KB */
    int tid  = threadIdx.x;
    int lane = tid & 31;
    int w    = tid >> 5;
    int mg   = w & 3;
    int ng   = w >> 2;
    int nBase = blockIdx.x * BLK_N;

    stage_V(Vs, V, nBase, tid);
    __syncthreads();

    int g = lane >> 2, c = lane & 3;
    int nCol0 = nBase + ng*128;

    for (int mt = 0; mt < MT_PER_BLK; mt++) {
        int rowBase = (blockIdx.y*MT_PER_BLK + mt) * BLK_M;
        int r0i = rowBase + mg*16 + g;
        int r1i = r0i + 8;

        uint32_t a[2][4];
        #pragma unroll
        for (int kh = 0; kh < 2; kh++) {
            a[kh][0] = f2tf32(LOG2E * g_hidden[(size_t)r0i*REC + kh*8 + c]);
            a[kh][1] = f2tf32(LOG2E * g_hidden[(size_t)r1i*REC + kh*8 + c]);
            a[kh][2] = f2tf32(LOG2E * g_hidden[(size_t)r0i*REC + kh*8 + c + 4]);
            a[kh][3] = f2tf32(LOG2E * g_hidden[(size_t)r1i*REC + kh*8 + c + 4]);
        }
        float sum0 = 0.f, sum1 = 0.f;

        #pragma unroll
        for (int t = 0; t < 16; t++) {
            int nc = ng*128 + t*8;
            float d[4] = {0.f, 0.f, 0.f, 0.f};
            #pragma unroll
            for (int kh = 0; kh < 2; kh++) {
                uint32_t b0 = Vs[(kh*8 + c    )*VS_STRIDE + nc + g];
                uint32_t b1 = Vs[(kh*8 + c + 4)*VS_STRIDE + nc + g];
                mma_tf32(d, a[kh], b0, b1);
            }
            int gcol = nCol0 + t*8 + 2*c;
            if (gcol < VOCAB) {
                sum0 += ex2(d[0]) + ex2(d[1]);
                sum1 += ex2(d[2]) + ex2(d[3]);
            }
        }

        sum0 += __shfl_xor_sync(0xffffffffu, sum0, 1);
        sum0 += __shfl_xor_sync(0xffffffffu, sum0, 2);
        sum1 += __shfl_xor_sync(0xffffffffu, sum1, 1);
        sum1 += __shfl_xor_sync(0xffffffffu, sum1, 2);
        if (c == 0) {
            int pi = blockIdx.x*4 + ng;
            g_part[(size_t)r0i*NPART + pi] = sum0;
            g_part[(size_t)r1i*NPART + pi] = sum1;
        }
    }
}

/* ---------------- lse[row] = log(sum of 252 partials) ---------------- */
__global__ void k_lse()
{
    int row = blockIdx.x*blockDim.x + threadIdx.x;
    if (row >= ROWS) return;
    const float4* p = (const float4*)(g_part + (size_t)row*NPART);
    float s = 0.f;
    #pragma unroll
    for (int i = 0; i < NPART/4; i++) {
        float4 v = p[i];
        s += (v.x + v.y) + (v.z + v.w);
    }
    g_lse[row] = logf(s);
}

/* ---------------- pass B: out = logit - lse, coalesced epilogue -------
   Per half (8 t-steps): fragments -> SBUF (conflict-free STS.64, stride
   264), then 512 threads stream 64x256 floats out as STG.128 where each
   warp covers two contiguous 256B row-runs (4 full lines / instr).      */
__global__ void __launch_bounds__(VTHREADS, 2)
k_vocab1(const float* __restrict__ V, float* __restrict__ out)
{
    extern __shared__ __align__(16) float dyn[];
    uint32_t* Vs  = (uint32_t*)dyn;                 /* 16 x 520 words */
    float* SBUF   = dyn + REC*VS_STRIDE;            /* 64 x 264 words */
    int tid  = threadIdx.x;
    int lane = tid & 31;
    int w    = tid >> 5;
    int mg   = w & 3;
    int ng   = w >> 2;
    int nBase = blockIdx.x * BLK_N;

    stage_V(Vs, V, nBase, tid);
    __syncthreads();

    int g = lane >> 2, c = lane & 3;

    for (int mt = 0; mt < MT_PER_BLK; mt++) {
        int rowBase = (blockIdx.y*MT_PER_BLK + mt) * BLK_M;
        int r0i = rowBase + mg*16 + g;
        int r1i = r0i + 8;

        uint32_t a[2][4];
        #pragma unroll
        for (int kh = 0; kh < 2; kh++) {
            a[kh][0] = f2tf32(g_hidden[(size_t)r0i*REC + kh*8 + c]);
            a[kh][1] = f2tf32(g_hidden[(size_t)r1i*REC + kh*8 + c]);
            a[kh][2] = f2tf32(g_hidden[(size_t)r0i*REC + kh*8 + c + 4]);
            a[kh][3] = f2tf32(g_hidden[(size_t)r1i*REC + kh*8 + c + 4]);
        }
        float lse0 = g_lse[r0i], lse1 = g_lse[r1i];
        int row_l = mg*16 + g;

        #pragma unroll
        for (int h = 0; h < 2; h++) {
            #pragma unroll
            for (int tt = 0; tt < 8; tt++) {
                int t = h*8 + tt;
                int nc = ng*128 + t*8;
                float d[4] = {0.f, 0.f, 0.f, 0.f};
                #pragma unroll
                for (int kh = 0; kh < 2; kh++) {
                    uint32_t b0 = Vs[(kh*8 + c    )*VS_STRIDE + nc + g];
                    uint32_t b1 = Vs[(kh*8 + c + 4)*VS_STRIDE + nc + g];
                    mma_tf32(d, a[kh], b0, b1);
                }
                int colb = ng*64 + tt*8 + 2*c;
                *(float2*)&SBUF[ row_l    *SB_STRIDE + colb] =
                    make_float2(d[0]-lse0, d[1]-lse0);
                *(float2*)&SBUF[(row_l+8)*SB_STRIDE + colb] =
                    make_float2(d[2]-lse1, d[3]-lse1);
            }
            __syncthreads();
            /* stream 64 rows x 256 cols: f -> (row rl, quad q) */
            #pragma unroll
            for (int it = 0; it < 8; it++) {
                int f  = it*VTHREADS + tid;
                int rl = f >> 6;
                int q  = f & 63;
                int ng2 = q >> 4;
                int off = (q & 15) * 4;
                int gcol = nBase + ng2*128 + h*64 + off;
                if (gcol < VOCAB) {
                    float4 vv = *(float4*)&SBUF[rl*SB_STRIDE + q*4];
                    __stcs((float4*)(out + (size_t)(rowBase+rl)*VOCAB + gcol), vv);
                }
            }
            __syncthreads();
        }
    }
}

extern "C" void kernel_launch(void* const* d_in, const int* in_sizes, int n_in,
                              void* d_out, int out_size)
{
    const int*   inp = (const int*)d_in[0];
    const float* emb = (const float*)d_in[1];
    const float* U   = (const float*)d_in[2];
    const float* W   = (const float*)d_in[3];
    const float* V   = (const float*)d_in[4];
    const float* b1  = (const float*)d_in[5];
    const float* b2  = (const float*)d_in[6];
    const float* h0  = (const float*)d_in[7];
    float* out = (float*)d_out;

    cudaFuncSetAttribute(k_vocab1, cudaFuncAttributeMaxDynamicSharedMemorySize,
                         DYN_SMEM_B);

    k_dummy<<<1, 32>>>();
    k_ih<<<(ROWS*REC + 255)/256, 256>>>(inp, emb, U, b1);
    k_rnn<<<NB, 32>>>(W, b2, h0);
    k_vocab0<<<dim3(NBLK_N, NBLK_M), VTHREADS>>>(V);
    k_lse<<<(ROWS + 255)/256, 256>>>();
    k_vocab1<<<dim3(NBLK_N, NBLK_M), VTHREADS, DYN_SMEM_B>>>(V, out);
}